// round 8
// baseline (speedup 1.0000x reference)
#include <cuda_runtime.h>
#include <cuda_bf16.h>
#include <math.h>
#include <stdint.h>
#include <mma.h>

using namespace nvcuda;

// ---------------------------------------------------------------------------
// RGCN, aggregate-first FUSED gather+GEMM per layer (no intermediate z/y).
//   per dst-tile, per relation r: Agg = S_r X  (gathered into SMEM, x L2-resident)
//                                 acc += Agg @ W_r   (wmma tf32)
//   h = relu(acc + sum_r b1_r) ; out = acc2 + sum_r b2_r
// CSR keyed by (relation, dst).
// ---------------------------------------------------------------------------

#define NREL 4
#define INF  128
#define HF   128
#define OUTF 64
#define MAXN 100000
#define MAXE 400000
#define SCAN_B 1024

__device__ float g_h[(size_t)MAXN * HF];
__device__ float g_deg_src[NREL * MAXN];
__device__ int   g_cnt[NREL * MAXN];
__device__ int   g_off[NREL * MAXN + 1];
__device__ int   g_cursor[NREL * MAXN];
__device__ int   g_bsum[512];
__device__ int   g_boff[512];
__device__ int   g_esrc[NREL * MAXE];
__device__ float g_ecoef[NREL * MAXE];
__device__ int   g_idx64;

__device__ __forceinline__ int load_idx(const void* p, size_t i, int is64) {
    return is64 ? (int)((const long long*)p)[i] : ((const int*)p)[i];
}

// ---------------------------------------------------------------------------
__global__ void init_kernel(const unsigned int* __restrict__ words, int n_words,
                            float* __restrict__ ds, int* __restrict__ cnt,
                            int* __restrict__ cur, int n) {
    if (blockIdx.x == 0) {
        int limit = n_words < 4096 ? n_words : 4096;
        int bad = 0;
        for (int i = 1 + 2 * (int)threadIdx.x; i < limit; i += 2 * (int)blockDim.x)
            bad |= (words[i] != 0u);
        bad = __syncthreads_or(bad);
        if (threadIdx.x == 0) g_idx64 = bad ? 0 : 1;
    }
    int i = blockIdx.x * blockDim.x + threadIdx.x;
    int st = gridDim.x * blockDim.x;
    for (int k = i; k < n; k += st) { ds[k] = 0.0f; cnt[k] = 0; cur[k] = 0; }
}

// per-(rel,node) degrees: ds = src degree (float), cnt = dst degree (int)
__global__ void degree_kernel(const void* __restrict__ src, const void* __restrict__ dst,
                              float* __restrict__ ds, int* __restrict__ cnt,
                              int E, int M) {
    int i = blockIdx.x * blockDim.x + threadIdx.x;
    if (i >= NREL * E) return;
    const int is64 = g_idx64;
    int r = i / E;
    int s = load_idx(src, i, is64);
    int d = load_idx(dst, i, is64);
    atomicAdd(&ds[r * M + s], 1.0f);
    atomicAdd(&cnt[r * M + d], 1);
}

// ---------------------------------------------------------------------------
// 3-pass multi-block exclusive scan of cnt[0..n) -> off[0..n]
__device__ __forceinline__ int block_incl_scan(int v, int* wsum) {
    const int lane = threadIdx.x & 31, wid = threadIdx.x >> 5;
    int s = v;
#pragma unroll
    for (int o = 1; o < 32; o <<= 1) {
        int t = __shfl_up_sync(~0u, s, o);
        if (lane >= o) s += t;
    }
    if (lane == 31) wsum[wid] = s;
    __syncthreads();
    if (wid == 0) {
        int ws = (lane < (SCAN_B / 32)) ? wsum[lane] : 0;
#pragma unroll
        for (int o = 1; o < 32; o <<= 1) {
            int t = __shfl_up_sync(~0u, ws, o);
            if (lane >= o) ws += t;
        }
        wsum[lane] = ws;
    }
    __syncthreads();
    return s + (wid > 0 ? wsum[wid - 1] : 0);
}

__global__ void scanA_kernel(const int* __restrict__ cnt, int* __restrict__ bsum, int n) {
    __shared__ int wsum[32];
    int i = blockIdx.x * SCAN_B + threadIdx.x;
    int v = (i < n) ? cnt[i] : 0;
    int s = block_incl_scan(v, wsum);
    if (threadIdx.x == SCAN_B - 1) bsum[blockIdx.x] = s;
}

__global__ void scanB_kernel(const int* __restrict__ bsum, int* __restrict__ boff,
                             int* __restrict__ off, int nb, int n) {
    const int lane = threadIdx.x;
    int carry = 0;
    for (int base = 0; base < nb; base += 32) {
        int i = base + lane;
        int v = (i < nb) ? bsum[i] : 0;
        int s = v;
#pragma unroll
        for (int o = 1; o < 32; o <<= 1) {
            int t = __shfl_up_sync(~0u, s, o);
            if (lane >= o) s += t;
        }
        if (i < nb) boff[i] = carry + s - v;
        carry += __shfl_sync(~0u, s, 31);
    }
    if (lane == 0) off[n] = carry;
}

__global__ void scanC_kernel(const int* __restrict__ cnt, const int* __restrict__ boff,
                             int* __restrict__ off, int n) {
    __shared__ int wsum[32];
    int i = blockIdx.x * SCAN_B + threadIdx.x;
    int v = (i < n) ? cnt[i] : 0;
    int s = block_incl_scan(v, wsum);
    if (i < n) off[i] = boff[blockIdx.x] + s - v;
}

// ---------------------------------------------------------------------------
// fill CSR slots (per rel,dst): esrc = src, ecoef = rsqrt(ds[src])*rsqrt(cnt[dst])
__global__ void fill_kernel(const void* __restrict__ src, const void* __restrict__ dst,
                            const float* __restrict__ ds, const int* __restrict__ cnt,
                            const int* __restrict__ off, int* __restrict__ cur,
                            int* __restrict__ esrc, float* __restrict__ ecoef,
                            int E, int M) {
    int i = blockIdx.x * blockDim.x + threadIdx.x;
    if (i >= NREL * E) return;
    const int is64 = g_idx64;
    int r = i / E;
    int s = load_idx(src, i, is64);
    int d = load_idx(dst, i, is64);
    int key = r * M + d;
    int pos = off[key] + atomicAdd(&cur[key], 1);
    esrc[pos] = s;
    ecoef[pos] = rsqrtf(fmaxf(ds[r * M + s], 1.0f)) *
                 rsqrtf(fmaxf((float)cnt[key], 1.0f));
}

// ---------------------------------------------------------------------------
// FUSED layer: per 128-dst tile, for each relation gather Agg = S_r X into
// SMEM (tf32), then wmma-accumulate Agg @ W_r. Epilogue adds bias sum (+relu).
// X: [M,128] fp32 (L2-resident). W: [NREL,128,NF]. C: [M,NF].
// ---------------------------------------------------------------------------
template <int NF, bool RELU>
__global__ __launch_bounds__(256)
void fused_layer_kernel(const float* __restrict__ X, const float* __restrict__ W,
                        const float* __restrict__ bias,
                        const int* __restrict__ off, const int* __restrict__ esrc,
                        const float* __restrict__ ecoef,
                        float* __restrict__ C, int M) {
    constexpr int NFRAG = NF / 16;
    extern __shared__ float sm[];
    float (*Agg)[132]    = (float(*)[132])sm;
    float (*Bs)[NF + 4]  = (float(*)[NF + 4])(sm + 128 * 132);

    const int tid  = threadIdx.x;
    const int wid  = tid >> 5;
    const int lane = tid & 31;
    const int row0 = blockIdx.x * 128;

    wmma::fragment<wmma::accumulator, 16, 16, 8, float> acc[NFRAG];
#pragma unroll
    for (int n = 0; n < NFRAG; n++) wmma::fill_fragment(acc[n], 0.0f);

    for (int r = 0; r < NREL; r++) {
        // stage W_r as tf32
        const float* Wr = W + (size_t)r * 128 * NF;
#pragma unroll
        for (int i = 0; i < (128 * NF / 4) / 256; i++) {
            int idx = tid + i * 256;
            int rr = idx / (NF / 4);
            int cc = (idx % (NF / 4)) * 4;
            float4 v = *(const float4*)(Wr + (size_t)rr * NF + cc);
            Bs[rr][cc + 0] = wmma::__float_to_tf32(v.x);
            Bs[rr][cc + 1] = wmma::__float_to_tf32(v.y);
            Bs[rr][cc + 2] = wmma::__float_to_tf32(v.z);
            Bs[rr][cc + 3] = wmma::__float_to_tf32(v.w);
        }
        // gather: warp owns 16 dst rows; lane owns float4 of 128 feats
#pragma unroll 1
        for (int i = 0; i < 16; i++) {
            const int lr = wid * 16 + i;
            const int d  = row0 + lr;
            float4 a = make_float4(0.f, 0.f, 0.f, 0.f);
            if (d < M) {
                const int key = r * M + d;
                const int e0 = __ldg(&off[key]), e1 = __ldg(&off[key + 1]);
#pragma unroll 4
                for (int e = e0; e < e1; e++) {
                    const int s   = __ldg(&esrc[e]);
                    const float c = __ldg(&ecoef[e]);
                    const float4 v = *(const float4*)(X + (size_t)s * 128 + lane * 4);
                    a.x += c * v.x; a.y += c * v.y; a.z += c * v.z; a.w += c * v.w;
                }
            }
            float4 t;
            t.x = wmma::__float_to_tf32(a.x);
            t.y = wmma::__float_to_tf32(a.y);
            t.z = wmma::__float_to_tf32(a.z);
            t.w = wmma::__float_to_tf32(a.w);
            *(float4*)(&Agg[lr][lane * 4]) = t;
        }
        __syncthreads();
        // accumulate Agg @ W_r
#pragma unroll
        for (int kf = 0; kf < 16; kf++) {
            wmma::fragment<wmma::matrix_a, 16, 16, 8, wmma::precision::tf32,
                           wmma::row_major> afrag;
            wmma::load_matrix_sync(afrag, &Agg[wid * 16][kf * 8], 132);
#pragma unroll
            for (int n = 0; n < NFRAG; n++) {
                wmma::fragment<wmma::matrix_b, 16, 16, 8, wmma::precision::tf32,
                               wmma::row_major> bfrag;
                wmma::load_matrix_sync(bfrag, &Bs[kf * 8][n * 16], NF + 4);
                wmma::mma_sync(acc[n], afrag, bfrag, acc[n]);
            }
        }
        __syncthreads();
    }

    // epilogue: frags -> SMEM -> biased (+relu) guarded global store
#pragma unroll
    for (int n = 0; n < NFRAG; n++)
        wmma::store_matrix_sync(&Agg[wid * 16][n * 16], acc[n], 132,
                                wmma::mem_row_major);
    __syncthreads();
#pragma unroll
    for (int i = 0; i < (128 * NF / 4) / 256; i++) {
        int idx = tid + i * 256;
        int rr = idx / (NF / 4);
        int cc = (idx % (NF / 4)) * 4;
        int d = row0 + rr;
        if (d < M) {
            float4 v = *(float4*)(&Agg[rr][cc]);
            v.x += bias[cc+0] + bias[NF+cc+0] + bias[2*NF+cc+0] + bias[3*NF+cc+0];
            v.y += bias[cc+1] + bias[NF+cc+1] + bias[2*NF+cc+1] + bias[3*NF+cc+1];
            v.z += bias[cc+2] + bias[NF+cc+2] + bias[2*NF+cc+2] + bias[3*NF+cc+2];
            v.w += bias[cc+3] + bias[NF+cc+3] + bias[2*NF+cc+3] + bias[3*NF+cc+3];
            if (RELU) {
                v.x = fmaxf(v.x, 0.f); v.y = fmaxf(v.y, 0.f);
                v.z = fmaxf(v.z, 0.f); v.w = fmaxf(v.w, 0.f);
            }
            *(float4*)(C + (size_t)d * NF + cc) = v;
        }
    }
}

// ---------------------------------------------------------------------------
extern "C" void kernel_launch(void* const* d_in, const int* in_sizes, int n_in,
                              void* d_out, int out_size) {
    const float* x    = (const float*)d_in[0];
    const void*  srcI = d_in[1];
    const void*  dstI = d_in[2];
    const float* W1   = (const float*)d_in[3];
    const float* b1   = (const float*)d_in[4];
    const float* W2   = (const float*)d_in[5];
    const float* b2   = (const float*)d_in[6];
    float*       out  = (float*)d_out;

    const int M = in_sizes[0] / INF;
    const int E = in_sizes[1] / NREL;
    const int tiles = (M + 127) / 128;
    const int NKEY = NREL * M;
    const int NB = (NKEY + SCAN_B - 1) / SCAN_B;

    float *h, *ds, *ecoef;
    int *cnt, *off, *cur, *esrc, *bsum, *boff;
    cudaGetSymbolAddress((void**)&h, g_h);
    cudaGetSymbolAddress((void**)&ds, g_deg_src);
    cudaGetSymbolAddress((void**)&cnt, g_cnt);
    cudaGetSymbolAddress((void**)&off, g_off);
    cudaGetSymbolAddress((void**)&cur, g_cursor);
    cudaGetSymbolAddress((void**)&esrc, g_esrc);
    cudaGetSymbolAddress((void**)&ecoef, g_ecoef);
    cudaGetSymbolAddress((void**)&bsum, g_bsum);
    cudaGetSymbolAddress((void**)&boff, g_boff);

    const int SMEM1 = (128 * 132 + 128 * (HF + 4)) * 4;   // 135168
    const int SMEM2 = (128 * 132 + 128 * (OUTF + 4)) * 4; // 102400
    cudaFuncSetAttribute((const void*)fused_layer_kernel<HF, true>,
                         cudaFuncAttributeMaxDynamicSharedMemorySize, SMEM1);
    cudaFuncSetAttribute((const void*)fused_layer_kernel<OUTF, false>,
                         cudaFuncAttributeMaxDynamicSharedMemorySize, SMEM2);

    // 1 init (+detect)
    init_kernel<<<512, 256>>>((const unsigned int*)srcI, NREL * E, ds, cnt, cur, NKEY);
    // 2 degrees
    degree_kernel<<<(NREL * E + 255) / 256, 256>>>(srcI, dstI, ds, cnt, E, M);
    // 3-5 scan of per-(rel,dst) counts
    scanA_kernel<<<NB, SCAN_B>>>(cnt, bsum, NKEY);
    scanB_kernel<<<1, 32>>>(bsum, boff, off, NB, NKEY);
    scanC_kernel<<<NB, SCAN_B>>>(cnt, boff, off, NKEY);
    // 6 fill CSR
    fill_kernel<<<(NREL * E + 255) / 256, 256>>>(srcI, dstI, ds, cnt,
                                                 off, cur, esrc, ecoef, E, M);
    // 7 fused layer 1: h = relu(sum_r (S_r x) W1_r + b1sum)
    fused_layer_kernel<HF, true><<<tiles, 256, SMEM1>>>(x, W1, b1, off, esrc,
                                                        ecoef, h, M);
    // 8 fused layer 2: out = sum_r (S_r h) W2_r + b2sum
    fused_layer_kernel<OUTF, false><<<tiles, 256, SMEM2>>>(h, W2, b2, off, esrc,
                                                           ecoef, out, M);
}

// round 9
// speedup vs baseline: 1.2557x; 1.2557x over previous
#include <cuda_runtime.h>
#include <cuda_bf16.h>
#include <math.h>
#include <stdint.h>
#include <mma.h>

using namespace nvcuda;

// ---------------------------------------------------------------------------
// RGCN. Layer 1 aggregate-first (gather on L2-resident x), layer 2 GEMM-first
// (gather on L2-hot y). CSR keyed by (relation, dst). wmma tf32 GEMMs.
//   agg_r = S_r x                 (gather_x, high occupancy, x L2-resident)
//   h     = relu(sum_r agg_r @ W1_r + b1sum)   (accumulating GEMM)
//   y_r   = h @ W2_r              (per-rel GEMM)
//   out   = sum_r gather(y_r) + b2sum          (gather2)
// ---------------------------------------------------------------------------

#define NREL 4
#define INF  128
#define HF   128
#define OUTF 64
#define MAXN 100000
#define MAXE 400000
#define MAXT ((MAXN + 127) / 128)
#define MAXP (MAXT * 128)
#define SCAN_B 1024

__device__ float g_agg[(size_t)NREL * MAXP * HF];   // agg_r (layer 1)
__device__ float g_y[(size_t)NREL * MAXP * OUTF];   // y_r (layer 2)
__device__ float g_h[(size_t)MAXN * HF];
__device__ float g_deg_src[NREL * MAXN];
__device__ int   g_cnt[NREL * MAXN];
__device__ int   g_off[NREL * MAXN + 1];
__device__ int   g_cursor[NREL * MAXN];
__device__ int   g_bsum[512];
__device__ int   g_boff[512];
__device__ int   g_esrc[NREL * MAXE];
__device__ float g_ecoef[NREL * MAXE];
__device__ int   g_idx64;

__device__ __forceinline__ int load_idx(const void* p, size_t i, int is64) {
    return is64 ? (int)((const long long*)p)[i] : ((const int*)p)[i];
}

// ---------------------------------------------------------------------------
__global__ void init_kernel(const unsigned int* __restrict__ words, int n_words,
                            float* __restrict__ ds, int* __restrict__ cnt,
                            int* __restrict__ cur, int n) {
    if (blockIdx.x == 0) {
        int limit = n_words < 4096 ? n_words : 4096;
        int bad = 0;
        for (int i = 1 + 2 * (int)threadIdx.x; i < limit; i += 2 * (int)blockDim.x)
            bad |= (words[i] != 0u);
        bad = __syncthreads_or(bad);
        if (threadIdx.x == 0) g_idx64 = bad ? 0 : 1;
    }
    int i = blockIdx.x * blockDim.x + threadIdx.x;
    int st = gridDim.x * blockDim.x;
    for (int k = i; k < n; k += st) { ds[k] = 0.0f; cnt[k] = 0; cur[k] = 0; }
}

__global__ void degree_kernel(const void* __restrict__ src, const void* __restrict__ dst,
                              float* __restrict__ ds, int* __restrict__ cnt,
                              int E, int M) {
    int i = blockIdx.x * blockDim.x + threadIdx.x;
    if (i >= NREL * E) return;
    const int is64 = g_idx64;
    int r = i / E;
    int s = load_idx(src, i, is64);
    int d = load_idx(dst, i, is64);
    atomicAdd(&ds[r * M + s], 1.0f);
    atomicAdd(&cnt[r * M + d], 1);
}

// ---------------------------------------------------------------------------
// 3-pass multi-block exclusive scan
__device__ __forceinline__ int block_incl_scan(int v, int* wsum) {
    const int lane = threadIdx.x & 31, wid = threadIdx.x >> 5;
    int s = v;
#pragma unroll
    for (int o = 1; o < 32; o <<= 1) {
        int t = __shfl_up_sync(~0u, s, o);
        if (lane >= o) s += t;
    }
    if (lane == 31) wsum[wid] = s;
    __syncthreads();
    if (wid == 0) {
        int ws = (lane < (SCAN_B / 32)) ? wsum[lane] : 0;
#pragma unroll
        for (int o = 1; o < 32; o <<= 1) {
            int t = __shfl_up_sync(~0u, ws, o);
            if (lane >= o) ws += t;
        }
        wsum[lane] = ws;
    }
    __syncthreads();
    return s + (wid > 0 ? wsum[wid - 1] : 0);
}

__global__ void scanA_kernel(const int* __restrict__ cnt, int* __restrict__ bsum, int n) {
    __shared__ int wsum[32];
    int i = blockIdx.x * SCAN_B + threadIdx.x;
    int v = (i < n) ? cnt[i] : 0;
    int s = block_incl_scan(v, wsum);
    if (threadIdx.x == SCAN_B - 1) bsum[blockIdx.x] = s;
}

__global__ void scanB_kernel(const int* __restrict__ bsum, int* __restrict__ boff,
                             int* __restrict__ off, int nb, int n) {
    const int lane = threadIdx.x;
    int carry = 0;
    for (int base = 0; base < nb; base += 32) {
        int i = base + lane;
        int v = (i < nb) ? bsum[i] : 0;
        int s = v;
#pragma unroll
        for (int o = 1; o < 32; o <<= 1) {
            int t = __shfl_up_sync(~0u, s, o);
            if (lane >= o) s += t;
        }
        if (i < nb) boff[i] = carry + s - v;
        carry += __shfl_sync(~0u, s, 31);
    }
    if (lane == 0) off[n] = carry;
}

__global__ void scanC_kernel(const int* __restrict__ cnt, const int* __restrict__ boff,
                             int* __restrict__ off, int n) {
    __shared__ int wsum[32];
    int i = blockIdx.x * SCAN_B + threadIdx.x;
    int v = (i < n) ? cnt[i] : 0;
    int s = block_incl_scan(v, wsum);
    if (i < n) off[i] = boff[blockIdx.x] + s - v;
}

// ---------------------------------------------------------------------------
__global__ void fill_kernel(const void* __restrict__ src, const void* __restrict__ dst,
                            const float* __restrict__ ds, const int* __restrict__ cnt,
                            const int* __restrict__ off, int* __restrict__ cur,
                            int* __restrict__ esrc, float* __restrict__ ecoef,
                            int E, int M) {
    int i = blockIdx.x * blockDim.x + threadIdx.x;
    if (i >= NREL * E) return;
    const int is64 = g_idx64;
    int r = i / E;
    int s = load_idx(src, i, is64);
    int d = load_idx(dst, i, is64);
    int key = r * M + d;
    int pos = off[key] + atomicAdd(&cur[key], 1);
    esrc[pos] = s;
    ecoef[pos] = rsqrtf(fmaxf(ds[r * M + s], 1.0f)) *
                 rsqrtf(fmaxf((float)cnt[key], 1.0f));
}

// ---------------------------------------------------------------------------
// gather_x: agg[r][d][0:128] = sum_e coef * x[src]; warp per (rel,dst) key.
// x is 51 MB -> L2-resident random reads.
__global__ __launch_bounds__(256)
void gatherx_kernel(const float* __restrict__ X, const int* __restrict__ off,
                    const int* __restrict__ esrc, const float* __restrict__ ecoef,
                    float* __restrict__ agg, int M, int Mp, int nkey) {
    const int key  = blockIdx.x * 8 + (threadIdx.x >> 5);
    const int lane = threadIdx.x & 31;
    if (key >= nkey) return;
    const int e0 = __ldg(&off[key]), e1 = __ldg(&off[key + 1]);
    float4 acc = make_float4(0.f, 0.f, 0.f, 0.f);
#pragma unroll 4
    for (int e = e0; e < e1; e++) {
        const int s   = __ldg(&esrc[e]);
        const float c = __ldg(&ecoef[e]);
        const float4 v = *(const float4*)(X + (size_t)s * 128 + lane * 4);
        acc.x += c * v.x; acc.y += c * v.y; acc.z += c * v.z; acc.w += c * v.w;
    }
    const int r = key / M, d = key - r * M;   // nkey = NREL*M
    *(float4*)(agg + ((size_t)r * Mp + d) * 128 + lane * 4) = acc;
}

// ---------------------------------------------------------------------------
// accumulating GEMM (layer 1): h = relu(sum_r agg_r @ W1_r + b1sum)
__global__ __launch_bounds__(256)
void gemm1_kernel(const float* __restrict__ Agg, const float* __restrict__ W,
                  const float* __restrict__ bias, float* __restrict__ H,
                  int M, int Mp) {
    extern __shared__ float sm[];
    float (*As)[132] = (float(*)[132])sm;
    float (*Bs)[132] = (float(*)[132])(sm + 128 * 132);

    const int tid  = threadIdx.x;
    const int wid  = tid >> 5;
    const int row0 = blockIdx.x * 128;

    wmma::fragment<wmma::accumulator, 16, 16, 8, float> acc[8];
#pragma unroll
    for (int n = 0; n < 8; n++) wmma::fill_fragment(acc[n], 0.0f);

    for (int r = 0; r < NREL; r++) {
        const float* Ar = Agg + (size_t)r * Mp * 128;
        const float* Wr = W + (size_t)r * 128 * 128;
#pragma unroll
        for (int i = 0; i < 16; i++) {
            int idx = tid + i * 256;
            int rr = idx >> 5;
            int cc = (idx & 31) * 4;
            int gr = row0 + rr;
            float4 v = make_float4(0.f, 0.f, 0.f, 0.f);
            if (gr < M) v = *(const float4*)(Ar + (size_t)gr * 128 + cc);
            As[rr][cc + 0] = wmma::__float_to_tf32(v.x);
            As[rr][cc + 1] = wmma::__float_to_tf32(v.y);
            As[rr][cc + 2] = wmma::__float_to_tf32(v.z);
            As[rr][cc + 3] = wmma::__float_to_tf32(v.w);
            float4 w = *(const float4*)(Wr + (size_t)rr * 128 + cc);
            Bs[rr][cc + 0] = wmma::__float_to_tf32(w.x);
            Bs[rr][cc + 1] = wmma::__float_to_tf32(w.y);
            Bs[rr][cc + 2] = wmma::__float_to_tf32(w.z);
            Bs[rr][cc + 3] = wmma::__float_to_tf32(w.w);
        }
        __syncthreads();
#pragma unroll
        for (int kf = 0; kf < 16; kf++) {
            wmma::fragment<wmma::matrix_a, 16, 16, 8, wmma::precision::tf32,
                           wmma::row_major> afrag;
            wmma::load_matrix_sync(afrag, &As[wid * 16][kf * 8], 132);
#pragma unroll
            for (int n = 0; n < 8; n++) {
                wmma::fragment<wmma::matrix_b, 16, 16, 8, wmma::precision::tf32,
                               wmma::row_major> bfrag;
                wmma::load_matrix_sync(bfrag, &Bs[kf * 8][n * 16], 132);
                wmma::mma_sync(acc[n], afrag, bfrag, acc[n]);
            }
        }
        __syncthreads();
    }

    // epilogue via SMEM, bias+relu, guarded store
#pragma unroll
    for (int n = 0; n < 8; n++)
        wmma::store_matrix_sync(&As[wid * 16][n * 16], acc[n], 132,
                                wmma::mem_row_major);
    __syncthreads();
#pragma unroll
    for (int i = 0; i < 16; i++) {
        int idx = tid + i * 256;
        int rr = idx >> 5;
        int cc = (idx & 31) * 4;
        int d = row0 + rr;
        if (d < M) {
            float4 v = *(float4*)(&As[rr][cc]);
            v.x = fmaxf(v.x + bias[cc+0] + bias[128+cc+0] + bias[256+cc+0] + bias[384+cc+0], 0.f);
            v.y = fmaxf(v.y + bias[cc+1] + bias[128+cc+1] + bias[256+cc+1] + bias[384+cc+1], 0.f);
            v.z = fmaxf(v.z + bias[cc+2] + bias[128+cc+2] + bias[256+cc+2] + bias[384+cc+2], 0.f);
            v.w = fmaxf(v.w + bias[cc+3] + bias[128+cc+3] + bias[256+cc+3] + bias[384+cc+3], 0.f);
            *(float4*)(H + (size_t)d * 128 + cc) = v;
        }
    }
}

// ---------------------------------------------------------------------------
// per-rel GEMM (layer 2): y_r = h @ W2_r
__global__ __launch_bounds__(256)
void gemm2_kernel(const float* __restrict__ A, const float* __restrict__ B,
                  float* __restrict__ C, int M, int Mp) {
    constexpr int NF = OUTF;
    extern __shared__ float sm[];
    float (*As)[132]    = (float(*)[132])sm;
    float (*Bs)[NF + 4] = (float(*)[NF + 4])(sm + 128 * 132);

    const int r    = blockIdx.y;
    const int row0 = blockIdx.x * 128;
    const int tid  = threadIdx.x;
    const int wid  = tid >> 5;
    const float* Br = B + (size_t)r * 128 * NF;

#pragma unroll
    for (int i = 0; i < 16; i++) {
        int idx = tid + i * 256;
        int rr = idx >> 5;
        int cc = (idx & 31) * 4;
        int gr = row0 + rr;
        float4 v = make_float4(0.f, 0.f, 0.f, 0.f);
        if (gr < M) v = *(const float4*)(A + (size_t)gr * 128 + cc);
        As[rr][cc + 0] = wmma::__float_to_tf32(v.x);
        As[rr][cc + 1] = wmma::__float_to_tf32(v.y);
        As[rr][cc + 2] = wmma::__float_to_tf32(v.z);
        As[rr][cc + 3] = wmma::__float_to_tf32(v.w);
    }
#pragma unroll
    for (int i = 0; i < (128 * NF / 4) / 256; i++) {
        int idx = tid + i * 256;
        int rr = idx / (NF / 4);
        int cc = (idx % (NF / 4)) * 4;
        float4 v = *(const float4*)(Br + (size_t)rr * NF + cc);
        Bs[rr][cc + 0] = wmma::__float_to_tf32(v.x);
        Bs[rr][cc + 1] = wmma::__float_to_tf32(v.y);
        Bs[rr][cc + 2] = wmma::__float_to_tf32(v.z);
        Bs[rr][cc + 3] = wmma::__float_to_tf32(v.w);
    }
    __syncthreads();

    wmma::fragment<wmma::accumulator, 16, 16, 8, float> acc[4];
#pragma unroll
    for (int n = 0; n < 4; n++) wmma::fill_fragment(acc[n], 0.0f);

#pragma unroll
    for (int kf = 0; kf < 16; kf++) {
        wmma::fragment<wmma::matrix_a, 16, 16, 8, wmma::precision::tf32,
                       wmma::row_major> a;
        wmma::load_matrix_sync(a, &As[wid * 16][kf * 8], 132);
#pragma unroll
        for (int n = 0; n < 4; n++) {
            wmma::fragment<wmma::matrix_b, 16, 16, 8, wmma::precision::tf32,
                           wmma::row_major> b;
            wmma::load_matrix_sync(b, &Bs[kf * 8][n * 16], NF + 4);
            wmma::mma_sync(acc[n], a, b, acc[n]);
        }
    }

    float* Crow = C + ((size_t)r * Mp + row0 + wid * 16) * NF;
#pragma unroll
    for (int n = 0; n < 4; n++)
        wmma::store_matrix_sync(Crow + n * 16, acc[n], NF, wmma::mem_row_major);
}

// ---------------------------------------------------------------------------
// gather2: half-warp per dst, 64 feats, 4 keyed edge lists; out = agg + b2sum
__global__ __launch_bounds__(256)
void gather2_kernel(const float* __restrict__ Y, const int* __restrict__ off,
                    const int* __restrict__ esrc, const float* __restrict__ ecoef,
                    const float* __restrict__ b2, float* __restrict__ out,
                    int M, int Mp) {
    const int warp = blockIdx.x * 8 + (threadIdx.x >> 5);
    const int lane = threadIdx.x & 31;
    const int d = warp * 2 + (lane >> 4);
    const int fl = lane & 15;
    if (d >= M) return;
    float4 acc = make_float4(0.f, 0.f, 0.f, 0.f);
    for (int r = 0; r < NREL; r++) {
        const int key = r * M + d;
        const int e0 = __ldg(&off[key]), e1 = __ldg(&off[key + 1]);
        const float* Yr = Y + (size_t)r * Mp * 64;
#pragma unroll 4
        for (int e = e0; e < e1; e++) {
            const int s   = __ldg(&esrc[e]);
            const float c = __ldg(&ecoef[e]);
            const float4 v = *(const float4*)(Yr + (size_t)s * 64 + fl * 4);
            acc.x += c * v.x; acc.y += c * v.y; acc.z += c * v.z; acc.w += c * v.w;
        }
    }
    const int f = fl * 4;
    float4 o;
    o.x = acc.x + b2[f+0] + b2[64+f+0] + b2[128+f+0] + b2[192+f+0];
    o.y = acc.y + b2[f+1] + b2[64+f+1] + b2[128+f+1] + b2[192+f+1];
    o.z = acc.z + b2[f+2] + b2[64+f+2] + b2[128+f+2] + b2[192+f+2];
    o.w = acc.w + b2[f+3] + b2[64+f+3] + b2[128+f+3] + b2[192+f+3];
    *(float4*)(out + (size_t)d * 64 + f) = o;
}

// ---------------------------------------------------------------------------
extern "C" void kernel_launch(void* const* d_in, const int* in_sizes, int n_in,
                              void* d_out, int out_size) {
    const float* x    = (const float*)d_in[0];
    const void*  srcI = d_in[1];
    const void*  dstI = d_in[2];
    const float* W1   = (const float*)d_in[3];
    const float* b1   = (const float*)d_in[4];
    const float* W2   = (const float*)d_in[5];
    const float* b2   = (const float*)d_in[6];
    float*       out  = (float*)d_out;

    const int M = in_sizes[0] / INF;
    const int E = in_sizes[1] / NREL;
    const int tiles = (M + 127) / 128;
    const int Mp = tiles * 128;
    const int NKEY = NREL * M;
    const int NB = (NKEY + SCAN_B - 1) / SCAN_B;

    float *agg, *y, *h, *ds, *ecoef;
    int *cnt, *off, *cur, *esrc, *bsum, *boff;
    cudaGetSymbolAddress((void**)&agg, g_agg);
    cudaGetSymbolAddress((void**)&y, g_y);
    cudaGetSymbolAddress((void**)&h, g_h);
    cudaGetSymbolAddress((void**)&ds, g_deg_src);
    cudaGetSymbolAddress((void**)&cnt, g_cnt);
    cudaGetSymbolAddress((void**)&off, g_off);
    cudaGetSymbolAddress((void**)&cur, g_cursor);
    cudaGetSymbolAddress((void**)&esrc, g_esrc);
    cudaGetSymbolAddress((void**)&ecoef, g_ecoef);
    cudaGetSymbolAddress((void**)&bsum, g_bsum);
    cudaGetSymbolAddress((void**)&boff, g_boff);

    const int SMEM1 = 2 * 128 * 132 * 4;                  // 135168
    const int SMEM2 = (128 * 132 + 128 * (OUTF + 4)) * 4; // 102400
    cudaFuncSetAttribute(gemm1_kernel, cudaFuncAttributeMaxDynamicSharedMemorySize, SMEM1);
    cudaFuncSetAttribute(gemm2_kernel, cudaFuncAttributeMaxDynamicSharedMemorySize, SMEM2);

    // 1 init (+detect)
    init_kernel<<<512, 256>>>((const unsigned int*)srcI, NREL * E, ds, cnt, cur, NKEY);
    // 2 degrees
    degree_kernel<<<(NREL * E + 255) / 256, 256>>>(srcI, dstI, ds, cnt, E, M);
    // 3-5 scan
    scanA_kernel<<<NB, SCAN_B>>>(cnt, bsum, NKEY);
    scanB_kernel<<<1, 32>>>(bsum, boff, off, NB, NKEY);
    scanC_kernel<<<NB, SCAN_B>>>(cnt, boff, off, NKEY);
    // 6 fill CSR
    fill_kernel<<<(NREL * E + 255) / 256, 256>>>(srcI, dstI, ds, cnt,
                                                 off, cur, esrc, ecoef, E, M);
    // 7 gather_x: agg_r = S_r x  (x L2-resident)
    gatherx_kernel<<<(NKEY + 7) / 8, 256>>>(x, off, esrc, ecoef, agg, M, Mp, NKEY);
    // 8 layer-1 accumulating GEMM: h = relu(sum_r agg_r @ W1_r + b1sum)
    gemm1_kernel<<<tiles, 256, SMEM1>>>(agg, W1, b1, h, M, Mp);
    // 9 layer-2 GEMM: y_r = h @ W2_r
    {
        dim3 grid(tiles, NREL);
        gemm2_kernel<<<grid, 256, SMEM2>>>(h, W2, y, M, Mp);
    }
    // 10 layer-2 gather: out = sum_r gather(y_r) + b2sum
    gather2_kernel<<<(M + 15) / 16, 256>>>(y, off, esrc, ecoef, b2, out, M, Mp);
}

// round 10
// speedup vs baseline: 1.5927x; 1.2683x over previous
#include <cuda_runtime.h>
#include <cuda_bf16.h>
#include <math.h>
#include <stdint.h>
#include <mma.h>

using namespace nvcuda;

// ---------------------------------------------------------------------------
// RGCN, GEMM-first + CSR gather (R7 structure, packed edge records).
//   z_r = x @ W1_r ; h[d] = relu(sum_e coef_e * z[rel_e][src_e] + b1sum)
//   y_r = h @ W2_r ; out[d] =   sum_e coef_e * y[rel_e][src_e] + b2sum
// ---------------------------------------------------------------------------

#define NREL 4
#define INF  128
#define HF   128
#define OUTF 64
#define MAXN 100000
#define MAXE 400000
#define MAXT ((MAXN + 127) / 128)
#define MAXP (MAXT * 128)
#define SCAN_B 1024

__device__ float g_z[(size_t)NREL * MAXP * HF];
__device__ float g_y[(size_t)NREL * MAXP * OUTF];
__device__ float g_h[(size_t)MAXN * HF];
__device__ float g_deg_src[NREL * MAXN];
__device__ float g_deg_dst[NREL * MAXN];
__device__ int   g_cnt[MAXN + 1];
__device__ int   g_off[MAXN + 1];
__device__ int   g_cursor[MAXN];
__device__ int   g_bsum[128];
__device__ int   g_boff[128];
__device__ int2  g_edge[NREL * MAXE];   // .x = src | rel<<20, .y = coef bits
__device__ int   g_idx64;

__device__ __forceinline__ int load_idx(const void* p, size_t i, int is64) {
    return is64 ? (int)((const long long*)p)[i] : ((const int*)p)[i];
}

// ---------------------------------------------------------------------------
__global__ void init_kernel(const unsigned int* __restrict__ words, int n_words,
                            float* __restrict__ ds, float* __restrict__ dd, int nrs,
                            int* __restrict__ cnt, int* __restrict__ cur, int n) {
    if (blockIdx.x == 0) {
        int limit = n_words < 4096 ? n_words : 4096;
        int bad = 0;
        for (int i = 1 + 2 * (int)threadIdx.x; i < limit; i += 2 * (int)blockDim.x)
            bad |= (words[i] != 0u);
        bad = __syncthreads_or(bad);
        if (threadIdx.x == 0) g_idx64 = bad ? 0 : 1;
    }
    int i = blockIdx.x * blockDim.x + threadIdx.x;
    int st = gridDim.x * blockDim.x;
    for (int k = i; k < nrs; k += st) { ds[k] = 0.0f; dd[k] = 0.0f; }
    for (int k = i; k < n; k += st)   { cnt[k] = 0; cur[k] = 0; }
}

__global__ void degree_kernel(const void* __restrict__ src, const void* __restrict__ dst,
                              float* __restrict__ ds, float* __restrict__ dd,
                              int* __restrict__ cnt, int E, int M) {
    int i = blockIdx.x * blockDim.x + threadIdx.x;
    if (i >= NREL * E) return;
    const int is64 = g_idx64;
    int r = i / E;
    int s = load_idx(src, i, is64);
    int d = load_idx(dst, i, is64);
    atomicAdd(&ds[r * M + s], 1.0f);
    atomicAdd(&dd[r * M + d], 1.0f);
    atomicAdd(&cnt[d], 1);
}

// ---------------------------------------------------------------------------
// 3-pass multi-block exclusive scan
__device__ __forceinline__ int block_incl_scan(int v, int* wsum) {
    const int lane = threadIdx.x & 31, wid = threadIdx.x >> 5;
    int s = v;
#pragma unroll
    for (int o = 1; o < 32; o <<= 1) {
        int t = __shfl_up_sync(~0u, s, o);
        if (lane >= o) s += t;
    }
    if (lane == 31) wsum[wid] = s;
    __syncthreads();
    if (wid == 0) {
        int ws = (lane < (SCAN_B / 32)) ? wsum[lane] : 0;
#pragma unroll
        for (int o = 1; o < 32; o <<= 1) {
            int t = __shfl_up_sync(~0u, ws, o);
            if (lane >= o) ws += t;
        }
        wsum[lane] = ws;
    }
    __syncthreads();
    return s + (wid > 0 ? wsum[wid - 1] : 0);
}

__global__ void scanA_kernel(const int* __restrict__ cnt, int* __restrict__ bsum, int n) {
    __shared__ int wsum[32];
    int i = blockIdx.x * SCAN_B + threadIdx.x;
    int v = (i < n) ? cnt[i] : 0;
    int s = block_incl_scan(v, wsum);
    if (threadIdx.x == SCAN_B - 1) bsum[blockIdx.x] = s;
}

__global__ void scanB_kernel(const int* __restrict__ bsum, int* __restrict__ boff,
                             int* __restrict__ off, int nb, int n) {
    const int lane = threadIdx.x;
    int carry = 0;
    for (int base = 0; base < nb; base += 32) {
        int i = base + lane;
        int v = (i < nb) ? bsum[i] : 0;
        int s = v;
#pragma unroll
        for (int o = 1; o < 32; o <<= 1) {
            int t = __shfl_up_sync(~0u, s, o);
            if (lane >= o) s += t;
        }
        if (i < nb) boff[i] = carry + s - v;
        carry += __shfl_sync(~0u, s, 31);
    }
    if (lane == 0) off[n] = carry;
}

__global__ void scanC_kernel(const int* __restrict__ cnt, const int* __restrict__ boff,
                             int* __restrict__ off, int n) {
    __shared__ int wsum[32];
    int i = blockIdx.x * SCAN_B + threadIdx.x;
    int v = (i < n) ? cnt[i] : 0;
    int s = block_incl_scan(v, wsum);
    if (i < n) off[i] = boff[blockIdx.x] + s - v;
}

// ---------------------------------------------------------------------------
__global__ void fill_kernel(const void* __restrict__ src, const void* __restrict__ dst,
                            const float* __restrict__ ds, const float* __restrict__ dd,
                            const int* __restrict__ off, int* __restrict__ cur,
                            int2* __restrict__ edge, int E, int M) {
    int i = blockIdx.x * blockDim.x + threadIdx.x;
    if (i >= NREL * E) return;
    const int is64 = g_idx64;
    int r = i / E;
    int s = load_idx(src, i, is64);
    int d = load_idx(dst, i, is64);
    int pos = off[d] + atomicAdd(&cur[d], 1);
    float coef = rsqrtf(fmaxf(ds[r * M + s], 1.0f)) *
                 rsqrtf(fmaxf(dd[r * M + d], 1.0f));
    edge[pos] = make_int2(s | (r << 20), __float_as_int(coef));
}

// ---------------------------------------------------------------------------
// wmma tf32 GEMM, full-K staging
// ---------------------------------------------------------------------------
template <int NF>
__global__ __launch_bounds__(256)
void wmma_gemm_kernel(const float* __restrict__ A, const float* __restrict__ B,
                      float* __restrict__ C, int M, int Mp) {
    constexpr int NFRAG = NF / 16;
    extern __shared__ float sm[];
    float (*As)[132]    = (float(*)[132])sm;
    float (*Bs)[NF + 4] = (float(*)[NF + 4])(sm + 128 * 132);

    const int r    = blockIdx.y;
    const int row0 = blockIdx.x * 128;
    const int tid  = threadIdx.x;
    const int wid  = tid >> 5;
    const float* Br = B + (size_t)r * 128 * NF;

#pragma unroll
    for (int i = 0; i < 16; i++) {
        int idx = tid + i * 256;
        int rr = idx >> 5;
        int cc = (idx & 31) * 4;
        int gr = row0 + rr;
        float4 v = make_float4(0.f, 0.f, 0.f, 0.f);
        if (gr < M) v = *(const float4*)(A + (size_t)gr * 128 + cc);
        As[rr][cc + 0] = wmma::__float_to_tf32(v.x);
        As[rr][cc + 1] = wmma::__float_to_tf32(v.y);
        As[rr][cc + 2] = wmma::__float_to_tf32(v.z);
        As[rr][cc + 3] = wmma::__float_to_tf32(v.w);
    }
#pragma unroll
    for (int i = 0; i < (128 * NF / 4) / 256; i++) {
        int idx = tid + i * 256;
        int rr = idx / (NF / 4);
        int cc = (idx % (NF / 4)) * 4;
        float4 v = *(const float4*)(Br + (size_t)rr * NF + cc);
        Bs[rr][cc + 0] = wmma::__float_to_tf32(v.x);
        Bs[rr][cc + 1] = wmma::__float_to_tf32(v.y);
        Bs[rr][cc + 2] = wmma::__float_to_tf32(v.z);
        Bs[rr][cc + 3] = wmma::__float_to_tf32(v.w);
    }
    __syncthreads();

    wmma::fragment<wmma::accumulator, 16, 16, 8, float> acc[NFRAG];
#pragma unroll
    for (int n = 0; n < NFRAG; n++) wmma::fill_fragment(acc[n], 0.0f);

#pragma unroll
    for (int kf = 0; kf < 16; kf++) {
        wmma::fragment<wmma::matrix_a, 16, 16, 8, wmma::precision::tf32,
                       wmma::row_major> a;
        wmma::load_matrix_sync(a, &As[wid * 16][kf * 8], 132);
#pragma unroll
        for (int n = 0; n < NFRAG; n++) {
            wmma::fragment<wmma::matrix_b, 16, 16, 8, wmma::precision::tf32,
                           wmma::row_major> b;
            wmma::load_matrix_sync(b, &Bs[kf * 8][n * 16], NF + 4);
            wmma::mma_sync(acc[n], a, b, acc[n]);
        }
    }

    float* Crow = C + ((size_t)r * Mp + row0 + wid * 16) * NF;
#pragma unroll
    for (int n = 0; n < NFRAG; n++)
        wmma::store_matrix_sync(Crow + n * 16, acc[n], NF, wmma::mem_row_major);
}

// ---------------------------------------------------------------------------
// gather1: warp per dst, 128 feats; h = relu(agg + b1sum)
__global__ __launch_bounds__(256)
void gather1_kernel(const float* __restrict__ Z, const int* __restrict__ off,
                    const int2* __restrict__ edge,
                    const float* __restrict__ b1, float* __restrict__ h,
                    int M, int Mp) {
    const int d = blockIdx.x * 8 + (threadIdx.x >> 5);
    const int lane = threadIdx.x & 31;
    if (d >= M) return;
    const int e0 = off[d], e1 = off[d + 1];
    float4 acc = make_float4(0.f, 0.f, 0.f, 0.f);
#pragma unroll 8
    for (int e = e0; e < e1; e++) {
        const int2 ed = __ldg(&edge[e]);
        const int s = ed.x & 0xFFFFF, r = ed.x >> 20;
        const float c = __int_as_float(ed.y);
        const float4 v = *(const float4*)(Z + ((size_t)r * Mp + s) * 128 + lane * 4);
        acc.x += c * v.x; acc.y += c * v.y; acc.z += c * v.z; acc.w += c * v.w;
    }
    const int f = lane * 4;
    float4 o;
    o.x = fmaxf(acc.x + b1[f+0] + b1[128+f+0] + b1[256+f+0] + b1[384+f+0], 0.f);
    o.y = fmaxf(acc.y + b1[f+1] + b1[128+f+1] + b1[256+f+1] + b1[384+f+1], 0.f);
    o.z = fmaxf(acc.z + b1[f+2] + b1[128+f+2] + b1[256+f+2] + b1[384+f+2], 0.f);
    o.w = fmaxf(acc.w + b1[f+3] + b1[128+f+3] + b1[256+f+3] + b1[384+f+3], 0.f);
    *(float4*)(h + (size_t)d * 128 + f) = o;
}

// gather2: half-warp per dst, 64 feats; out = agg + b2sum
__global__ __launch_bounds__(256)
void gather2_kernel(const float* __restrict__ Y, const int* __restrict__ off,
                    const int2* __restrict__ edge,
                    const float* __restrict__ b2, float* __restrict__ out,
                    int M, int Mp) {
    const int warp = blockIdx.x * 8 + (threadIdx.x >> 5);
    const int lane = threadIdx.x & 31;
    const int d = warp * 2 + (lane >> 4);
    const int fl = lane & 15;
    if (d >= M) return;
    const int e0 = off[d], e1 = off[d + 1];
    float4 acc = make_float4(0.f, 0.f, 0.f, 0.f);
#pragma unroll 8
    for (int e = e0; e < e1; e++) {
        const int2 ed = __ldg(&edge[e]);
        const int s = ed.x & 0xFFFFF, r = ed.x >> 20;
        const float c = __int_as_float(ed.y);
        const float4 v = *(const float4*)(Y + ((size_t)r * Mp + s) * 64 + fl * 4);
        acc.x += c * v.x; acc.y += c * v.y; acc.z += c * v.z; acc.w += c * v.w;
    }
    const int f = fl * 4;
    float4 o;
    o.x = acc.x + b2[f+0] + b2[64+f+0] + b2[128+f+0] + b2[192+f+0];
    o.y = acc.y + b2[f+1] + b2[64+f+1] + b2[128+f+1] + b2[192+f+1];
    o.z = acc.z + b2[f+2] + b2[64+f+2] + b2[128+f+2] + b2[192+f+2];
    o.w = acc.w + b2[f+3] + b2[64+f+3] + b2[128+f+3] + b2[192+f+3];
    *(float4*)(out + (size_t)d * 64 + f) = o;
}

// ---------------------------------------------------------------------------
extern "C" void kernel_launch(void* const* d_in, const int* in_sizes, int n_in,
                              void* d_out, int out_size) {
    const float* x    = (const float*)d_in[0];
    const void*  srcI = d_in[1];
    const void*  dstI = d_in[2];
    const float* W1   = (const float*)d_in[3];
    const float* b1   = (const float*)d_in[4];
    const float* W2   = (const float*)d_in[5];
    const float* b2   = (const float*)d_in[6];
    float*       out  = (float*)d_out;

    const int M = in_sizes[0] / INF;
    const int E = in_sizes[1] / NREL;
    const int tiles = (M + 127) / 128;
    const int Mp = tiles * 128;
    const int NB = (M + SCAN_B - 1) / SCAN_B;

    float *z, *y, *h, *ds, *dd;
    int *cnt, *off, *cur, *bsum, *boff;
    int2 *edge;
    cudaGetSymbolAddress((void**)&z, g_z);
    cudaGetSymbolAddress((void**)&y, g_y);
    cudaGetSymbolAddress((void**)&h, g_h);
    cudaGetSymbolAddress((void**)&ds, g_deg_src);
    cudaGetSymbolAddress((void**)&dd, g_deg_dst);
    cudaGetSymbolAddress((void**)&cnt, g_cnt);
    cudaGetSymbolAddress((void**)&off, g_off);
    cudaGetSymbolAddress((void**)&cur, g_cursor);
    cudaGetSymbolAddress((void**)&edge, g_edge);
    cudaGetSymbolAddress((void**)&bsum, g_bsum);
    cudaGetSymbolAddress((void**)&boff, g_boff);

    const int SMEM1 = (128 * 132 + 128 * (HF + 4)) * 4;
    const int SMEM2 = (128 * 132 + 128 * (OUTF + 4)) * 4;
    cudaFuncSetAttribute(wmma_gemm_kernel<HF>,
                         cudaFuncAttributeMaxDynamicSharedMemorySize, SMEM1);
    cudaFuncSetAttribute(wmma_gemm_kernel<OUTF>,
                         cudaFuncAttributeMaxDynamicSharedMemorySize, SMEM2);

    // 1 init (+detect)
    init_kernel<<<512, 256>>>((const unsigned int*)srcI, NREL * E,
                              ds, dd, NREL * M, cnt, cur, M);
    // 2 degrees + counts
    degree_kernel<<<(NREL * E + 255) / 256, 256>>>(srcI, dstI, ds, dd, cnt, E, M);
    // 3 scanA
    scanA_kernel<<<NB, SCAN_B>>>(cnt, bsum, M);
    // 4 layer-1 GEMM  (ncu capture slot)
    {
        dim3 grid(tiles, NREL);
        wmma_gemm_kernel<HF><<<grid, 256, SMEM1>>>(x, W1, z, M, Mp);
    }
    // 5-6 finish scan
    scanB_kernel<<<1, 32>>>(bsum, boff, off, NB, M);
    scanC_kernel<<<NB, SCAN_B>>>(cnt, boff, off, M);
    // 7 fill CSR
    fill_kernel<<<(NREL * E + 255) / 256, 256>>>(srcI, dstI, ds, dd,
                                                 off, cur, edge, E, M);
    // 8 layer-1 gather (+bias+relu)
    gather1_kernel<<<(M + 7) / 8, 256>>>(z, off, edge, b1, h, M, Mp);
    // 9 layer-2 GEMM
    {
        dim3 grid(tiles, NREL);
        wmma_gemm_kernel<OUTF><<<grid, 256, SMEM2>>>(h, W2, y, M, Mp);
    }
    // 10 layer-2 gather (+bias)
    gather2_kernel<<<(M + 15) / 16, 256>>>(y, off, edge, b2, out, M, Mp);
}